// round 17
// baseline (speedup 1.0000x reference)
#include <cuda_runtime.h>

#define Bn   128
#define Dm   256
#define HD   64
#define TT   30
#define IMGN 16384
#define NSTEPS 29
#define ENC_KC 32
#define NB   32     // persistent blocks

__device__ float g_s[Bn * Dm];
__device__ float g_preds[TT * Bn * Dm];
__device__ float g_encP[ENC_KC * Bn * Dm];
__device__ float g_buf[2][Bn * 3 * Dm];          // double-buffered qkv
__device__ float g_Wqt[4 * 768 * 256];           // transposed weights [l][c][k]
__device__ float g_Wot[4 * 256 * 256];
__device__ float g_W1t[4 * 256 * 256];
__device__ float g_W2t[4 * 256 * 256];
__device__ unsigned g_barcnt;

// ---------------- f32x2 helpers ----------------
__device__ __forceinline__ unsigned long long pk2(float a) {
    unsigned long long r;
    asm("mov.b64 %0,{%1,%1};" : "=l"(r) : "f"(a));
    return r;
}
__device__ __forceinline__ unsigned long long pk2p(float a, float b) {
    unsigned long long r;
    asm("mov.b64 %0,{%1,%2};" : "=l"(r) : "f"(a), "f"(b));
    return r;
}
__device__ __forceinline__ void fma2(unsigned long long& d, unsigned long long a,
                                     unsigned long long b) {
    asm("fma.rn.f32x2 %0,%1,%2,%0;" : "+l"(d) : "l"(a), "l"(b));
}
__device__ __forceinline__ void unpk2(unsigned long long a, float& lo, float& hi) {
    asm("mov.b64 {%0,%1},%2;" : "=f"(lo), "=f"(hi) : "l"(a));
}

// ---------------- LayerNorm helpers ----------------
__device__ __forceinline__ float ln_row(float v, const float* __restrict__ g,
                                        const float* __restrict__ b, int tid) {
    __shared__ float wb[8][2];
    __shared__ float tot[2];
    int lane = tid & 31, w = tid >> 5;
    float s0 = v, s1 = v * v;
    #pragma unroll
    for (int o = 16; o; o >>= 1) {
        s0 += __shfl_xor_sync(0xffffffffu, s0, o);
        s1 += __shfl_xor_sync(0xffffffffu, s1, o);
    }
    if (!lane) { wb[w][0] = s0; wb[w][1] = s1; }
    __syncthreads();
    if (tid < 2) {
        float t = 0.f;
        #pragma unroll
        for (int k = 0; k < 8; k++) t += wb[k][tid];
        tot[tid] = t;
    }
    __syncthreads();
    float mu  = tot[0] * (1.f / 256.f);
    float var = tot[1] * (1.f / 256.f) - mu * mu;
    float r = (v - mu) * rsqrtf(var + 1e-5f) * g[tid] + b[tid];
    __syncthreads();
    return r;
}

__device__ __forceinline__ void ln4(const float v[4], float out[4],
                                    const float* __restrict__ g,
                                    const float* __restrict__ b, int tid) {
    __shared__ float wb[8][8];
    __shared__ float tot[8];
    int lane = tid & 31, w = tid >> 5;
    float s[8];
    #pragma unroll
    for (int r = 0; r < 4; r++) { s[r] = v[r]; s[4 + r] = v[r] * v[r]; }
    #pragma unroll
    for (int o = 16; o; o >>= 1) {
        #pragma unroll
        for (int i = 0; i < 8; i++) s[i] += __shfl_xor_sync(0xffffffffu, s[i], o);
    }
    if (!lane) {
        #pragma unroll
        for (int i = 0; i < 8; i++) wb[w][i] = s[i];
    }
    __syncthreads();
    if (tid < 8) {
        float t = 0.f;
        #pragma unroll
        for (int k = 0; k < 8; k++) t += wb[k][tid];
        tot[tid] = t;
    }
    __syncthreads();
    float gg = g[tid], bb = b[tid];
    #pragma unroll
    for (int r = 0; r < 4; r++) {
        float mu  = tot[r] * (1.f / 256.f);
        float var = tot[4 + r] * (1.f / 256.f) - mu * mu;
        out[r] = (v[r] - mu) * rsqrtf(var + 1e-5f) * gg + bb;
    }
    __syncthreads();
}

// ---------------- grid barrier ----------------
__global__ void k_rst() { g_barcnt = 0u; }

__device__ __forceinline__ void gbar(unsigned& tgt) {
    __syncthreads();
    if (threadIdx.x == 0) {
        __threadfence();
        atomicAdd(&g_barcnt, 1u);
        tgt += NB;
        volatile unsigned* p = &g_barcnt;
        while (*p < tgt) { }
        __threadfence();
    }
    __syncthreads();
}

// ---------------- weight transpose: src [4][256][C] -> dst [4][C][256] ----------------
__global__ void k_tw(const float* __restrict__ src, float* __restrict__ dst, int C) {
    int idx = blockIdx.x * 256 + threadIdx.x;
    int total = 4 * C * 256;
    if (idx >= total) return;
    int k = idx & 255;
    int rem = idx >> 8;
    int c = rem % C;
    int l = rem / C;
    dst[idx] = src[(size_t)(l * 256 + k) * C + c];
}

// ---------------- encoder ----------------
__global__ void k_enc(const float* __restrict__ x, const float* __restrict__ W) {
    __shared__ float xst[512 * 20];
    int tid = threadIdx.x;
    int k0 = blockIdx.x * 512;
    int r0 = blockIdx.y * 16;
    for (int idx = tid; idx < 16 * 512; idx += 256) {
        int r = idx >> 9, kk = idx & 511;
        xst[kk * 20 + r] = x[(size_t)(r0 + r) * (TT * IMGN) + k0 + kk];
    }
    __syncthreads();
    float acc[16];
    #pragma unroll
    for (int r = 0; r < 16; r++) acc[r] = 0.f;
    const float* wp = W + (size_t)k0 * Dm + tid;
    for (int kk = 0; kk < 512; kk++) {
        float w = wp[(size_t)kk * Dm];
        const float* ap = &xst[kk * 20];
        float4 a0 = *(const float4*)(ap);
        float4 a1 = *(const float4*)(ap + 4);
        float4 a2 = *(const float4*)(ap + 8);
        float4 a3 = *(const float4*)(ap + 12);
        acc[0]  += a0.x * w; acc[1]  += a0.y * w; acc[2]  += a0.z * w; acc[3]  += a0.w * w;
        acc[4]  += a1.x * w; acc[5]  += a1.y * w; acc[6]  += a1.z * w; acc[7]  += a1.w * w;
        acc[8]  += a2.x * w; acc[9]  += a2.y * w; acc[10] += a2.z * w; acc[11] += a2.w * w;
        acc[12] += a3.x * w; acc[13] += a3.y * w; acc[14] += a3.z * w; acc[15] += a3.w * w;
    }
    #pragma unroll
    for (int r = 0; r < 16; r++)
        g_encP[(size_t)(blockIdx.x * Bn + r0 + r) * Dm + tid] = acc[r];
}

__global__ void k_encred(const float* __restrict__ eb,
                         const float* __restrict__ g, const float* __restrict__ b) {
    int tid = threadIdx.x, row = blockIdx.x;
    float v = eb[tid];
    #pragma unroll 4
    for (int c = 0; c < ENC_KC; c++)
        v += g_encP[(size_t)(c * Bn + row) * Dm + tid];
    float o = ln_row(v, g, b, tid);
    g_s[row * Dm + tid] = o;
    g_preds[row * Dm + tid] = o;
}

// ---------------- persistent recurrence ----------------
// smem layout (floats):
#define OFF_HT   0                       // [256 cols][4 rows]
#define OFF_OWN  1024                    // own qkv rows [4][768]
#define OFF_OT   4096                    // attn out [256 cols][4 rows]
#define OFF_TT   5120                    // ffn mid [256 cols][4 rows]
#define OFF_KT   6144                    // Kt [2][64 d][136]
#define OFF_V    23552                   // V  [2][128 k][68]
#define OFF_SS   40960                   // softmax a [8 warps][132]
#define SMEM_FLOATS 42016
#define SMEM_RECUR (SMEM_FLOATS * 4)

__global__ void __launch_bounds__(256, 1)
k_recur(const float* __restrict__ bqkv, const float* __restrict__ bo,
        const float* __restrict__ b1, const float* __restrict__ b2,
        const float* __restrict__ ln1_g, const float* __restrict__ ln1_b,
        const float* __restrict__ ln2_g, const float* __restrict__ ln2_b,
        const float* __restrict__ dg, const float* __restrict__ db) {
    extern __shared__ float sm[];
    float* shT  = sm + OFF_HT;
    float* sown = sm + OFF_OWN;
    float* shoT = sm + OFF_OT;
    float* shtT = sm + OFF_TT;
    float* Kt   = sm + OFF_KT;
    float* Vs   = sm + OFF_V;
    float* ss   = sm + OFF_SS;

    int tid = threadIdx.x;
    int warp = tid >> 5, lane = tid & 31;
    int r0g = blockIdx.x * 4;
    unsigned tgt = 0;

    // load initial state rows
    #pragma unroll
    for (int r = 0; r < 4; r++)
        shT[tid * 4 + r] = g_s[(r0g + r) * Dm + tid];
    __syncthreads();

    for (int it = 0; it < NSTEPS * 4; ++it) {
        int l = it & 3;
        int t = it >> 2;
        int buf = it & 1;
        float* qb = g_buf[buf];

        // ======== qkv GEMM: 4 rows x 768 cols ========
        {
            const float* Wq = g_Wqt + (size_t)l * 768 * 256;
            const float* w0 = Wq + (size_t)tid * 256;
            const float* w1 = Wq + (size_t)(tid + 256) * 256;
            const float* w2 = Wq + (size_t)(tid + 512) * 256;
            unsigned long long acc[6];
            #pragma unroll
            for (int i = 0; i < 6; i++) acc[i] = 0ULL;
            for (int k = 0; k < 256; k += 4) {
                float4 wa = *(const float4*)(w0 + k);
                float4 wb4 = *(const float4*)(w1 + k);
                float4 wc = *(const float4*)(w2 + k);
                float wav[4] = {wa.x, wa.y, wa.z, wa.w};
                float wbv[4] = {wb4.x, wb4.y, wb4.z, wb4.w};
                float wcv[4] = {wc.x, wc.y, wc.z, wc.w};
                #pragma unroll
                for (int j = 0; j < 4; j++) {
                    float4 a = *(const float4*)&shT[(k + j) * 4];
                    unsigned long long a01 = pk2p(a.x, a.y);
                    unsigned long long a23 = pk2p(a.z, a.w);
                    unsigned long long wA = pk2(wav[j]);
                    unsigned long long wB = pk2(wbv[j]);
                    unsigned long long wC = pk2(wcv[j]);
                    fma2(acc[0], a01, wA); fma2(acc[1], a23, wA);
                    fma2(acc[2], a01, wB); fma2(acc[3], a23, wB);
                    fma2(acc[4], a01, wC); fma2(acc[5], a23, wC);
                }
            }
            #pragma unroll
            for (int i = 0; i < 3; i++) {
                int c = tid + i * 256;
                float v0, v1, v2, v3;
                unpk2(acc[2 * i], v0, v1);
                unpk2(acc[2 * i + 1], v2, v3);
                float bb = bqkv[l * 768 + c];
                float vals[4] = {v0 + bb, v1 + bb, v2 + bb, v3 + bb};
                #pragma unroll
                for (int r = 0; r < 4; r++) {
                    qb[(r0g + r) * 768 + c] = vals[r];
                    sown[r * 768 + c] = vals[r];
                }
            }
        }

        gbar(tgt);   // all blocks' K/V published

        // ======== attention (2-head groups) ========
        for (int hg = 0; hg < 2; hg++) {
            for (int idx = tid; idx < 4096; idx += 256) {
                int d4 = idx & 15;
                int row = (idx >> 4) & 127;
                int hp = idx >> 11;
                int h = hg * 2 + hp;
                float4 kv = *(const float4*)&qb[row * 768 + 256 + h * 64 + d4 * 4];
                float* ktb = Kt + hp * 8704;
                ktb[(d4 * 4 + 0) * 136 + row] = kv.x;
                ktb[(d4 * 4 + 1) * 136 + row] = kv.y;
                ktb[(d4 * 4 + 2) * 136 + row] = kv.z;
                ktb[(d4 * 4 + 3) * 136 + row] = kv.w;
                float4 vv = *(const float4*)&qb[row * 768 + 512 + h * 64 + d4 * 4];
                *(float4*)&Vs[hp * 8704 + row * 68 + d4 * 4] = vv;
            }
            __syncthreads();

            int q = warp >> 1, hp = warp & 1, h = hg * 2 + hp;
            const float* qrow = sown + q * 768 + h * 64;
            const float* ktb = Kt + hp * 8704 + lane;
            float s0 = 0.f, s1 = 0.f, s2 = 0.f, s3 = 0.f;
            #pragma unroll 8
            for (int d = 0; d < 64; d++) {
                float qv = qrow[d];
                const float* kr = ktb + d * 136;
                s0 += qv * kr[0];  s1 += qv * kr[32];
                s2 += qv * kr[64]; s3 += qv * kr[96];
            }
            s0 *= 0.125f; s1 *= 0.125f; s2 *= 0.125f; s3 *= 0.125f;
            float m = fmaxf(fmaxf(s0, s1), fmaxf(s2, s3));
            #pragma unroll
            for (int o = 16; o; o >>= 1) m = fmaxf(m, __shfl_xor_sync(0xffffffffu, m, o));
            float e0 = __expf(s0 - m), e1 = __expf(s1 - m);
            float e2 = __expf(s2 - m), e3 = __expf(s3 - m);
            float sum = e0 + e1 + e2 + e3;
            #pragma unroll
            for (int o = 16; o; o >>= 1) sum += __shfl_xor_sync(0xffffffffu, sum, o);
            float inv = 1.f / sum;
            float* arow = ss + warp * 132;
            arow[lane]      = e0 * inv;
            arow[lane + 32] = e1 * inv;
            arow[lane + 64] = e2 * inv;
            arow[lane + 96] = e3 * inv;
            __syncwarp();
            float o0 = 0.f, o1 = 0.f;
            const float* vb = Vs + hp * 8704 + 2 * lane;
            #pragma unroll 4
            for (int k = 0; k < 128; k++) {
                float a = arow[k];
                float2 vv = *(const float2*)(vb + k * 68);
                o0 += a * vv.x; o1 += a * vv.y;
            }
            shoT[(h * 64 + 2 * lane) * 4 + q]     = o0;
            shoT[(h * 64 + 2 * lane + 1) * 4 + q] = o1;
            __syncthreads();
        }

        // ======== Wo + residual + LN1 ========
        {
            const float* Wp = g_Wot + (size_t)l * 65536 + (size_t)tid * 256;
            unsigned long long b01 = 0ULL, b23 = 0ULL;
            for (int k = 0; k < 256; k += 4) {
                float4 w = *(const float4*)(Wp + k);
                float wv[4] = {w.x, w.y, w.z, w.w};
                #pragma unroll
                for (int j = 0; j < 4; j++) {
                    float4 a = *(const float4*)&shoT[(k + j) * 4];
                    unsigned long long w2 = pk2(wv[j]);
                    fma2(b01, pk2p(a.x, a.y), w2);
                    fma2(b23, pk2p(a.z, a.w), w2);
                }
            }
            float v[4], o[4];
            unpk2(b01, v[0], v[1]);
            unpk2(b23, v[2], v[3]);
            float4 hres = *(const float4*)&shT[tid * 4];
            float bb = bo[l * 256 + tid];
            v[0] += bb + hres.x; v[1] += bb + hres.y;
            v[2] += bb + hres.z; v[3] += bb + hres.w;
            ln4(v, o, ln1_g + l * 256, ln1_b + l * 256, tid);
            *(float4*)&shT[tid * 4] = make_float4(o[0], o[1], o[2], o[3]);
        }
        __syncthreads();

        // ======== FFN + residual + LN2 (+ final decn LN) ========
        {
            const float* W1p = g_W1t + (size_t)l * 65536 + (size_t)tid * 256;
            unsigned long long b01 = 0ULL, b23 = 0ULL;
            for (int k = 0; k < 256; k += 4) {
                float4 w = *(const float4*)(W1p + k);
                float wv[4] = {w.x, w.y, w.z, w.w};
                #pragma unroll
                for (int j = 0; j < 4; j++) {
                    float4 a = *(const float4*)&shT[(k + j) * 4];
                    unsigned long long w2 = pk2(wv[j]);
                    fma2(b01, pk2p(a.x, a.y), w2);
                    fma2(b23, pk2p(a.z, a.w), w2);
                }
            }
            float t0, t1, t2, t3;
            unpk2(b01, t0, t1);
            unpk2(b23, t2, t3);
            float bb = b1[l * 256 + tid];
            *(float4*)&shtT[tid * 4] = make_float4(
                fmaxf(t0 + bb, 0.f), fmaxf(t1 + bb, 0.f),
                fmaxf(t2 + bb, 0.f), fmaxf(t3 + bb, 0.f));
        }
        __syncthreads();
        {
            const float* W2p = g_W2t + (size_t)l * 65536 + (size_t)tid * 256;
            unsigned long long b01 = 0ULL, b23 = 0ULL;
            for (int k = 0; k < 256; k += 4) {
                float4 w = *(const float4*)(W2p + k);
                float wv[4] = {w.x, w.y, w.z, w.w};
                #pragma unroll
                for (int j = 0; j < 4; j++) {
                    float4 a = *(const float4*)&shtT[(k + j) * 4];
                    unsigned long long w2 = pk2(wv[j]);
                    fma2(b01, pk2p(a.x, a.y), w2);
                    fma2(b23, pk2p(a.z, a.w), w2);
                }
            }
            float v[4], o[4];
            unpk2(b01, v[0], v[1]);
            unpk2(b23, v[2], v[3]);
            float4 hres = *(const float4*)&shT[tid * 4];
            float bb = b2[l * 256 + tid];
            v[0] += bb + hres.x; v[1] += bb + hres.y;
            v[2] += bb + hres.z; v[3] += bb + hres.w;
            ln4(v, o, ln2_g + l * 256, ln2_b + l * 256, tid);
            if (l == 3) {
                float o2[4];
                ln4(o, o2, dg, db, tid);
                *(float4*)&shT[tid * 4] = make_float4(o2[0], o2[1], o2[2], o2[3]);
                #pragma unroll
                for (int r = 0; r < 4; r++)
                    g_preds[(size_t)(t + 1) * Bn * Dm + (r0g + r) * Dm + tid] = o2[r];
            } else {
                *(float4*)&shT[tid * 4] = make_float4(o[0], o[1], o[2], o[3]);
            }
        }
        __syncthreads();
    }
}

// ---------------- decoder (packed f32x2) ----------------
__global__ void __launch_bounds__(256)
k_dec(const float* __restrict__ W, const float* __restrict__ bias,
      float* __restrict__ out) {
    __shared__ float As[256 * 32];
    int tid = threadIdx.x;
    int i = blockIdx.x * 512 + tid * 2;
    int r0 = blockIdx.y * 32;
    for (int idx = tid; idx < 32 * 256; idx += 256) {
        int r = idx & 31, k = idx >> 5;
        int rg = r0 + r;
        int bb = rg / TT;
        int t = rg - bb * TT;
        As[k * 32 + r] = g_preds[(size_t)(t * Bn + bb) * Dm + k];
    }
    __syncthreads();
    unsigned long long acc[32];
    #pragma unroll
    for (int r = 0; r < 32; r++) acc[r] = 0ULL;
    const unsigned long long* wp = (const unsigned long long*)(W + i);
    for (int k = 0; k < 256; k++) {
        unsigned long long w2 = wp[(size_t)k * (IMGN / 2)];
        const float* ap = &As[k * 32];
        #pragma unroll
        for (int j = 0; j < 8; j++) {
            float4 a = *(const float4*)(ap + 4 * j);
            fma2(acc[4 * j + 0], pk2(a.x), w2);
            fma2(acc[4 * j + 1], pk2(a.y), w2);
            fma2(acc[4 * j + 2], pk2(a.z), w2);
            fma2(acc[4 * j + 3], pk2(a.w), w2);
        }
    }
    float2 bd = *(const float2*)&bias[i];
    #pragma unroll
    for (int r = 0; r < 32; r++) {
        float lo, hi;
        unpk2(acc[r], lo, hi);
        float2 o;
        o.x = lo + bd.x;
        o.y = hi + bd.y;
        *(float2*)&out[(size_t)(r0 + r) * IMGN + i] = o;
    }
}

extern "C" void kernel_launch(void* const* d_in, const int* in_sizes, int n_in,
                              void* d_out, int out_size) {
    const float* x      = (const float*)d_in[0];
    const float* enc_W  = (const float*)d_in[1];
    const float* enc_b  = (const float*)d_in[2];
    const float* encn_g = (const float*)d_in[3];
    const float* encn_b = (const float*)d_in[4];
    const float* dec_W  = (const float*)d_in[5];
    const float* dec_b  = (const float*)d_in[6];
    const float* decn_g = (const float*)d_in[7];
    const float* decn_b = (const float*)d_in[8];
    const float* Wqkv   = (const float*)d_in[9];
    const float* bqkv   = (const float*)d_in[10];
    const float* Wo     = (const float*)d_in[11];
    const float* bo     = (const float*)d_in[12];
    const float* W1     = (const float*)d_in[13];
    const float* b1     = (const float*)d_in[14];
    const float* W2     = (const float*)d_in[15];
    const float* b2     = (const float*)d_in[16];
    const float* ln1_g  = (const float*)d_in[17];
    const float* ln1_b  = (const float*)d_in[18];
    const float* ln2_g  = (const float*)d_in[19];
    const float* ln2_b  = (const float*)d_in[20];
    float* out = (float*)d_out;

    static int smem_set = 0;
    if (!smem_set) {
        cudaFuncSetAttribute(k_recur, cudaFuncAttributeMaxDynamicSharedMemorySize,
                             SMEM_RECUR);
        smem_set = 1;
    }

    float* wqt;  cudaGetSymbolAddress((void**)&wqt, g_Wqt);   // resolved host-side, no alloc

    // one-time-per-launch weight transposes (deterministic, cheap)
    k_tw<<<(4 * 768 * 256 + 255) / 256, 256>>>(Wqkv, wqt, 768);
    float* wot; cudaGetSymbolAddress((void**)&wot, g_Wot);
    float* w1t; cudaGetSymbolAddress((void**)&w1t, g_W1t);
    float* w2t; cudaGetSymbolAddress((void**)&w2t, g_W2t);
    k_tw<<<(4 * 256 * 256 + 255) / 256, 256>>>(Wo, wot, 256);
    k_tw<<<(4 * 256 * 256 + 255) / 256, 256>>>(W1, w1t, 256);
    k_tw<<<(4 * 256 * 256 + 255) / 256, 256>>>(W2, w2t, 256);

    k_rst<<<1, 1>>>();
    k_enc<<<dim3(ENC_KC, 8), 256>>>(x, enc_W);
    k_encred<<<Bn, 256>>>(enc_b, encn_g, encn_b);

    k_recur<<<NB, 256, SMEM_RECUR>>>(bqkv, bo, b1, b2,
                                     ln1_g, ln1_b, ln2_g, ln2_b,
                                     decn_g, decn_b);

    k_dec<<<dim3(32, 120), 256>>>(dec_W, dec_b, out);
}